// round 14
// baseline (speedup 1.0000x reference)
#include <cuda_runtime.h>
#include <cuda_bf16.h>
#include <cstdint>
#include <math.h>

// ---------------- problem constants ----------------
#define BB   16
#define LL   4096
#define NR   (BB*LL)      // 65536 rows
#define DD   512
#define CC   128
#define HH   4
#define DK   32
#define MM   512
#define NCHUNK 32
#define SCALE_F 0.17677669529663687f

// ---------------- device scratch ----------------
__device__ unsigned g_Qm[(size_t)NR * CC];
__device__ unsigned g_Km[(size_t)NR * CC];
__device__ unsigned g_Vm[(size_t)NR * CC];
__device__ float    g_part[(size_t)NCHUNK * BB * HH * DK * DK];
__device__ float    g_attn[BB * HH * DK * DK];
// transposed + split weights: [n][k] layout, k contiguous
__device__ unsigned short g_WqT_hi [128 * 512], g_WqT_lo [128 * 512];
__device__ unsigned short g_WkvT_hi[256 * 512], g_WkvT_lo[256 * 512];
__device__ unsigned short g_WqoT_hi[512 * 128], g_WqoT_lo[512 * 128];
__device__ unsigned short g_WoT_hi [16 * 512 * 128], g_WoT_lo[16 * 512 * 128];

// ---------------- helpers ----------------
__device__ __forceinline__ void split2(float x, unsigned short& h, unsigned short& l)
{
    __nv_bfloat16 hb = __float2bfloat16(x);
    float r = x - __bfloat162float(hb);
    __nv_bfloat16 lb = __float2bfloat16(r);
    h = __bfloat16_as_ushort(hb);
    l = __bfloat16_as_ushort(lb);
}
__device__ __forceinline__ unsigned packf(float x)
{
    unsigned short h, l; split2(x, h, l);
    return (unsigned)h | ((unsigned)l << 16);
}
__device__ __forceinline__ float unpackf(unsigned u)
{
    float h = __bfloat162float(__ushort_as_bfloat16((unsigned short)(u & 0xffffu)));
    float l = __bfloat162float(__ushort_as_bfloat16((unsigned short)(u >> 16)));
    return h + l;
}
__device__ __forceinline__ void mma16816(float* c, const unsigned* a, const unsigned* b)
{
    asm volatile(
        "mma.sync.aligned.m16n8k16.row.col.f32.bf16.bf16.f32 "
        "{%0,%1,%2,%3}, {%4,%5,%6,%7}, {%8,%9}, {%0,%1,%2,%3};"
        : "+f"(c[0]), "+f"(c[1]), "+f"(c[2]), "+f"(c[3])
        : "r"(a[0]), "r"(a[1]), "r"(a[2]), "r"(a[3]), "r"(b[0]), "r"(b[1]));
}
__device__ __forceinline__ uint32_t smem_u32(const void* p)
{
    uint32_t a;
    asm("{ .reg .u64 t; cvta.to.shared.u64 t, %1; cvt.u32.u64 %0, t; }" : "=r"(a) : "l"(p));
    return a;
}
__device__ __forceinline__ void ldsm4(uint32_t* r, uint32_t a)
{
    asm volatile("ldmatrix.sync.aligned.m8n8.x4.shared.b16 {%0,%1,%2,%3}, [%4];"
        : "=r"(r[0]), "=r"(r[1]), "=r"(r[2]), "=r"(r[3]) : "r"(a));
}
__device__ __forceinline__ void cp16(uint32_t dst, const void* src)
{
    asm volatile("cp.async.cg.shared.global [%0], [%1], 16;"
        :: "r"(dst), "l"(__cvta_generic_to_global(src)) : "memory");
}
#define CP_COMMIT() asm volatile("cp.async.commit_group;" ::: "memory")
#define CP_WAIT0()  asm volatile("cp.async.wait_group 0;" ::: "memory")

// =====================================================================
// k_prep: build transposed, bf16-split weight copies.
// =====================================================================
__global__ void __launch_bounds__(256) k_prep(
    const float* __restrict__ Wq, const float* __restrict__ Wk,
    const float* __restrict__ Wv, const float* __restrict__ Wqo)
{
    int e = blockIdx.x * 256 + threadIdx.x;      // 0..262143
    unsigned short h, l;
    if (e < 65536) {                              // WqT [128][512]
        int n = e >> 9, k = e & 511;
        split2(Wq[(size_t)k * 128 + n], h, l);
        g_WqT_hi[(size_t)n * 512 + k] = h; g_WqT_lo[(size_t)n * 512 + k] = l;
    } else if (e < 196608) {                      // WkvT [256][512]
        int e2 = e - 65536;
        int n = e2 >> 9, k = e2 & 511;
        float v = (n < 128) ? Wk[(size_t)k * 128 + n] : Wv[(size_t)k * 128 + (n - 128)];
        split2(v, h, l);
        g_WkvT_hi[(size_t)n * 512 + k] = h; g_WkvT_lo[(size_t)n * 512 + k] = l;
    } else {                                      // WqoT [512][128]
        int e2 = e - 196608;
        int n = e2 >> 7, k = e2 & 127;
        split2(Wqo[(size_t)k * 512 + n], h, l);
        g_WqoT_hi[(size_t)n * 128 + k] = h; g_WqoT_lo[(size_t)n * 128 + k] = l;
    }
}

// =====================================================================
// K1: QKV projection (Round-10 structure). grid (NR/128, 3):
// y=0 Qm, y=1 Km, y=2 Vm. 8 warps 4Mx2N, warp 32x64, BK=32.
// B tiles via cp.async; A tiles manual (fp32 split). 2 bufs x 40KB.
// =====================================================================
__global__ void __launch_bounds__(256) k_qkv_mma(
    const float* __restrict__ Q_in, const float* __restrict__ KV_in,
    const float* __restrict__ bq, const float* __restrict__ bk,
    const float* __restrict__ bv)
{
    extern __shared__ __align__(16) char smem[];
    const int t = threadIdx.x;
    const int lane = t & 31, wid = t >> 5;
    const int g = lane >> 2, tig = lane & 3;
    const int warpM = wid & 3, warpN = wid >> 2;
    const int row0 = blockIdx.x * 128;
    const int y = blockIdx.y;
    const uint32_t sb = smem_u32(smem);

    const float* A = (y == 0) ? Q_in : KV_in;
    const unsigned short* WT_hi = (y == 0) ? g_WqT_hi : (g_WkvT_hi + (size_t)(y - 1) * 128 * 512);
    const unsigned short* WT_lo = (y == 0) ? g_WqT_lo : (g_WkvT_lo + (size_t)(y - 1) * 128 * 512);
    const float* bias = (y == 0) ? bq : ((y == 1) ? bk : bv);
    unsigned* outp = (y == 0) ? g_Qm : ((y == 1) ? g_Km : g_Vm);

    // layout per buffer: As_hi @0, As_lo @10240, Bs_hi @20480, Bs_lo @30720
    const uint32_t BUF = 40960;
    const uint32_t aoff = (uint32_t)((warpM * 32 + (lane & 7) + ((lane >> 3) & 1) * 8) * 80
                                     + ((lane >> 4) & 1) * 16);
    const uint32_t boff = (uint32_t)((warpN * 64 + (lane & 7) + ((lane >> 4) & 1) * 8) * 80
                                     + ((lane >> 3) & 1) * 16);

    float c[2][8][4];
#pragma unroll
    for (int mi = 0; mi < 2; mi++)
#pragma unroll
        for (int ni = 0; ni < 8; ni++)
#pragma unroll
            for (int q = 0; q < 4; q++) c[mi][ni][q] = 0.f;

    float4 av[4];

    auto cpB = [&](int cc, int buf) {
        const int kk = cc * 32;
        const uint32_t dstb = sb + buf * BUF;
#pragma unroll
        for (int i = 0; i < 2; i++) {
            int f = i * 256 + t, n = f >> 2, k8 = (f & 3) * 8;
            size_t idx = (size_t)n * DD + kk + k8;
            int off = n * 80 + k8 * 2;
            cp16(dstb + 20480 + off, WT_hi + idx);
            cp16(dstb + 30720 + off, WT_lo + idx);
        }
        CP_COMMIT();
    };
    auto gloadA = [&](int cc) {
        const int kk = cc * 32;
#pragma unroll
        for (int i = 0; i < 4; i++) {
            int f = i * 256 + t, r = f >> 3, kq = (f & 7) * 4;
            av[i] = *(const float4*)(A + (size_t)(row0 + r) * DD + kk + kq);
        }
    };
    auto sstoreA = [&](int buf) {
        char* b0 = smem + buf * BUF;
#pragma unroll
        for (int i = 0; i < 4; i++) {
            int f = i * 256 + t, r = f >> 3, kq = (f & 7) * 4;
            unsigned short h0,h1,h2,h3,l0,l1,l2,l3;
            split2(av[i].x, h0, l0); split2(av[i].y, h1, l1);
            split2(av[i].z, h2, l2); split2(av[i].w, h3, l3);
            int off = r * 80 + kq * 2;
            *(uint2*)(b0 + off) = make_uint2((unsigned)h0 | ((unsigned)h1 << 16),
                                             (unsigned)h2 | ((unsigned)h3 << 16));
            *(uint2*)(b0 + 10240 + off) = make_uint2((unsigned)l0 | ((unsigned)l1 << 16),
                                                     (unsigned)l2 | ((unsigned)l3 << 16));
        }
    };
    auto compute = [&](int buf) {
        const uint32_t base = sb + buf * BUF;
#pragma unroll
        for (int ks = 0; ks < 2; ks++) {
            const uint32_t ko = ks * 32;
            uint32_t ah[2][4], al[2][4];
            ldsm4(ah[0], base + aoff + ko);
            ldsm4(ah[1], base + aoff + 1280 + ko);
            ldsm4(al[0], base + 10240 + aoff + ko);
            ldsm4(al[1], base + 10240 + aoff + 1280 + ko);
#pragma unroll
            for (int p = 0; p < 4; p++) {
                uint32_t bh[4], bl[4];
                ldsm4(bh, base + 20480 + boff + p * 1280 + ko);
                ldsm4(bl, base + 30720 + boff + p * 1280 + ko);
#pragma unroll
                for (int q = 0; q < 2; q++)
#pragma unroll
                    for (int mi = 0; mi < 2; mi++) {
                        mma16816(c[mi][2*p+q], ah[mi], bh + 2*q);
                        mma16816(c[mi][2*p+q], ah[mi], bl + 2*q);
                        mma16816(c[mi][2*p+q], al[mi], bh + 2*q);
                    }
            }
        }
    };

    cpB(0, 0);
    gloadA(0);
    sstoreA(0);
    CP_WAIT0();
    __syncthreads();
#pragma unroll 1
    for (int cc = 0; cc < 16; cc++) {
        const int buf = cc & 1;
        if (cc < 15) {
            cpB(cc + 1, buf ^ 1);     // async copy overlaps compute below
            gloadA(cc + 1);
        }
        compute(buf);
        if (cc < 15) {
            sstoreA(buf ^ 1);
            CP_WAIT0();
            __syncthreads();
        }
    }

    // epilogue: bias + pack + store
#pragma unroll
    for (int mi = 0; mi < 2; mi++) {
        int r0 = row0 + warpM * 32 + mi * 16 + g;
#pragma unroll
        for (int ni = 0; ni < 8; ni++) {
            int col = warpN * 64 + ni * 8 + tig * 2;
            float b0f = bias[col], b1f = bias[col + 1];
            unsigned p00 = packf(c[mi][ni][0] + b0f);
            unsigned p01 = packf(c[mi][ni][1] + b1f);
            unsigned p10 = packf(c[mi][ni][2] + b0f);
            unsigned p11 = packf(c[mi][ni][3] + b1f);
            *(uint2*)&outp[(size_t)r0 * CC + col]       = make_uint2(p00, p01);
            *(uint2*)&outp[(size_t)(r0 + 8) * CC + col] = make_uint2(p10, p11);
        }
    }
}

// =====================================================================
// K2: partial scores (reads packed Qm/Km).
// =====================================================================
__global__ void __launch_bounds__(256) k_scores()
{
    __shared__ float Qs[128][32];
    __shared__ float Ks[128][32];
    const int t = threadIdx.x;
    const int chunk = blockIdx.x;
    const int bh = blockIdx.y;
    const int b = bh >> 2, h = bh & 3;
    const int rowbase = b * LL + chunk * 128;

#pragma unroll
    for (int i = 0; i < 4; i++) {
        int f = i * 256 + t;
        int r = f >> 3, j = (f & 7) * 4;
        uint4 q = *(const uint4*)(g_Qm + (size_t)(rowbase + r) * CC + h * DK + j);
        uint4 k = *(const uint4*)(g_Km + (size_t)(rowbase + r) * CC + h * DK + j);
        Qs[r][j+0] = unpackf(q.x); Qs[r][j+1] = unpackf(q.y);
        Qs[r][j+2] = unpackf(q.z); Qs[r][j+3] = unpackf(q.w);
        Ks[r][j+0] = unpackf(k.x); Ks[r][j+1] = unpackf(k.y);
        Ks[r][j+2] = unpackf(k.z); Ks[r][j+3] = unpackf(k.w);
    }
    __syncthreads();

    const int tile = t & 63, ly = t >> 6;
    const int d0 = (tile >> 3) * 4, e0 = (tile & 7) * 4;
    float acc[4][4];
#pragma unroll
    for (int r = 0; r < 4; r++)
#pragma unroll
        for (int c = 0; c < 4; c++) acc[r][c] = 0.f;

    for (int l = ly; l < 128; l += 4) {
        float4 q = *(const float4*)&Qs[l][d0];
        float4 k = *(const float4*)&Ks[l][e0];
        float qa[4] = {q.x,q.y,q.z,q.w};
        float ka[4] = {k.x,k.y,k.z,k.w};
#pragma unroll
        for (int r = 0; r < 4; r++)
#pragma unroll
            for (int c = 0; c < 4; c++)
                acc[r][c] = fmaf(qa[r], ka[c], acc[r][c]);
    }
    __syncthreads();
    float* red = &Qs[0][0];
#pragma unroll
    for (int r = 0; r < 4; r++)
#pragma unroll
        for (int c = 0; c < 4; c++) red[t*16 + r*4 + c] = acc[r][c];
    __syncthreads();
    if (t < 64) {
        const int dd0 = (t >> 3) * 4, ee0 = (t & 7) * 4;
#pragma unroll
        for (int i = 0; i < 16; i++) {
            float s = red[t*16+i] + red[(t+64)*16+i] + red[(t+128)*16+i] + red[(t+192)*16+i];
            int r = i >> 2, c = i & 3;
            g_part[(size_t)chunk * 65536 + bh*1024 + (dd0+r)*32 + (ee0+c)] = s;
        }
    }
}

// =====================================================================
// K3: reduce + softmax.
// =====================================================================
__global__ void __launch_bounds__(1024) k_softmax(float* __restrict__ attn_out)
{
    const int bh = blockIdx.x;
    const int t = threadIdx.x;
    float s = 0.f;
#pragma unroll
    for (int c = 0; c < NCHUNK; c++) s += g_part[(size_t)c*65536 + bh*1024 + t];
    s *= SCALE_F;
    float m = s;
#pragma unroll
    for (int o = 16; o; o >>= 1) m = fmaxf(m, __shfl_xor_sync(0xffffffffu, m, o));
    float ex = expf(s - m);
    float sum = ex;
#pragma unroll
    for (int o = 16; o; o >>= 1) sum += __shfl_xor_sync(0xffffffffu, sum, o);
    float a = ex / sum;
    g_attn[bh*1024 + t] = a;
    if (attn_out) attn_out[bh*1024 + t] = a;
}

// =====================================================================
// K4: WoEff transposed + bf16-split: g_WoT[b][m][e] = sum_d attn*Wo.
// =====================================================================
__global__ void __launch_bounds__(256) k_woeff(const float* __restrict__ Wo)
{
    __shared__ float at[4096];
    __shared__ float wo_s[128][32];
    const int m0 = blockIdx.x * 32;
    const int b  = blockIdx.y;
    const int t  = threadIdx.x;
#pragma unroll
    for (int i = 0; i < 4; i++) {
        int f = i*256 + t;
        *(float4*)&at[f*4] = *(const float4*)(g_attn + (size_t)b*4096 + f*4);
    }
#pragma unroll
    for (int i = 0; i < 4; i++) {
        int f = i*256 + t;
        int r = f >> 3, c = (f & 7) * 4;
        *(float4*)&wo_s[r][c] = *(const float4*)(Wo + (size_t)r*MM + m0 + c);
    }
    __syncthreads();
    const int tx = t & 31, ty = t >> 5;
#pragma unroll
    for (int i = 0; i < 16; i++) {
        int he = ty + 8*i;
        int h = he >> 5, e = he & 31;
        float s = 0.f;
#pragma unroll
        for (int d = 0; d < 32; d++)
            s = fmaf(at[h*1024 + d*32 + e], wo_s[h*32+d][tx], s);
        unsigned short hh, ll; split2(s, hh, ll);
        size_t o = ((size_t)b * 512 + (m0 + tx)) * 128 + he;
        g_WoT_hi[o] = hh; g_WoT_lo[o] = ll;
    }
}

// =====================================================================
// K5: fused final GEMM + LN (Round-10 winner + cp.async B path).
// 256 threads, 8 warps 2Mx4N, BM=64, BN=512, BK=16, warp 32x128.
// Row stride 48B. Dyn smem 2 x 54KB.
// =====================================================================
__global__ void __launch_bounds__(256) k_fgemm_ln(
    const float* __restrict__ bqo, const float* __restrict__ bo,
    const float* __restrict__ gamma, const float* __restrict__ beta,
    float* __restrict__ Y)
{
    extern __shared__ __align__(16) char smem[];
    __shared__ float redS[4][64], redQ[4][64];

    const int t = threadIdx.x;
    const int lane = t & 31, wid = t >> 5;
    const int g = lane >> 2, tig = lane & 3;
    const int warpM = wid & 1, warpN = wid >> 1;   // 2M x 4N
    const int row0 = blockIdx.x * 64;
    const int b = row0 >> 12;
    const int kc = tig * 2;
    const uint32_t sb = smem_u32(smem);

    // per buffer: As_hi @0 (3072), As_lo @3072, Bs_hi @6144 (24576), Bs_lo @30720
    const uint32_t BUF = 55296;
    const uint32_t aoff = (uint32_t)((warpM * 32 + (lane & 7) + ((lane >> 3) & 1) * 8) * 48
                                     + ((lane >> 4) & 1) * 16);
    const uint32_t boff = (uint32_t)((warpN * 128 + (lane & 7) + ((lane >> 4) & 1) * 8) * 48
                                     + ((lane >> 3) & 1) * 16);

    float c[2][16][4];
#pragma unroll
    for (int mi = 0; mi < 2; mi++)
#pragma unroll
        for (int ni = 0; ni < 16; ni++)
#pragma unroll
            for (int q = 0; q < 4; q++) c[mi][ni][q] = 0.f;

    uint4 av;

    auto cpB = [&](int cc, int buf) {
        const int kk = cc * 16;
        const uint32_t dstb = sb + buf * BUF;
#pragma unroll
        for (int i = 0; i < 4; i++) {
            int f = i * 256 + t;
            int n = f >> 1, k8 = (f & 1) * 8;
            size_t idx;
            const unsigned short *sh_, *sl_;
            if (kk < 128) {
                idx = (size_t)n * 128 + kk + k8;
                sh_ = g_WqoT_hi; sl_ = g_WqoT_lo;
            } else {
                idx = ((size_t)b * 512 + n) * 128 + (kk - 128) + k8;
                sh_ = g_WoT_hi; sl_ = g_WoT_lo;
            }
            int off = n * 48 + k8 * 2;
            cp16(dstb + 6144 + off, sh_ + idx);
            cp16(dstb + 30720 + off, sl_ + idx);
        }
        CP_COMMIT();
    };
    auto gloadA = [&](int cc) {
        const int kk = cc * 16;
        int r = t >> 2, kq = (t & 3) * 4;
        int kg = kk + kq;
        const unsigned* src = (kk < 128)
            ? (g_Qm + (size_t)(row0 + r) * CC + kg)
            : (g_Vm + (size_t)(row0 + r) * CC + (kg - 128));
        av = *(const uint4*)src;
    };
    auto sstoreA = [&](int buf) {
        char* b0 = smem + buf * BUF;
        int r = t >> 2, kq = (t & 3) * 4;
        int off = r * 48 + kq * 2;
        *(uint2*)(b0 + off) = make_uint2((av.x & 0xffffu) | ((av.y & 0xffffu) << 16),
                                         (av.z & 0xffffu) | ((av.w & 0xffffu) << 16));
        *(uint2*)(b0 + 3072 + off) = make_uint2((av.x >> 16) | (av.y & 0xffff0000u),
                                                (av.z >> 16) | (av.w & 0xffff0000u));
    };
    auto compute = [&](int buf) {
        const uint32_t base = sb + buf * BUF;
        uint32_t ah[2][4], al[2][4];
        ldsm4(ah[0], base + aoff);
        ldsm4(ah[1], base + aoff + 768);
        ldsm4(al[0], base + 3072 + aoff);
        ldsm4(al[1], base + 3072 + aoff + 768);
#pragma unroll
        for (int p = 0; p < 8; p++) {
            uint32_t bh[4], bl[4];
            ldsm4(bh, base + 6144 + boff + p * 768);
            ldsm4(bl, base + 30720 + boff + p * 768);
#pragma unroll
            for (int q = 0; q < 2; q++)
#pragma unroll
                for (int mi = 0; mi < 2; mi++) {
                    mma16816(c[mi][2*p+q], ah[mi], bh + 2*q);
                    mma16816(c[mi][2*p+q], ah[mi], bl + 2*q);
                    mma16816(c[mi][2*p+q], al[mi], bh + 2*q);
                }
        }
    };

    cpB(0, 0);
    gloadA(0);
    sstoreA(0);
    CP_WAIT0();
    __syncthreads();
#pragma unroll 1
    for (int cc = 0; cc < 16; cc++) {
        const int buf = cc & 1;
        if (cc < 15) {
            cpB(cc + 1, buf ^ 1);     // async copy overlaps compute below
            gloadA(cc + 1);
        }
        compute(buf);
        if (cc < 15) {
            sstoreA(buf ^ 1);
            CP_WAIT0();
            __syncthreads();
        }
    }

    // ---- epilogue: bias, LN stats, normalize, store ----
#pragma unroll
    for (int mi = 0; mi < 2; mi++) {
        float sA = 0.f, qA = 0.f, sB = 0.f, qB = 0.f;
#pragma unroll
        for (int ni = 0; ni < 16; ni++) {
            int col = warpN * 128 + ni * 8 + kc;
            float b0 = bqo[col] + bo[col];
            float b1 = bqo[col + 1] + bo[col + 1];
            float x0 = c[mi][ni][0] + b0, x1 = c[mi][ni][1] + b1;
            float x2 = c[mi][ni][2] + b0, x3 = c[mi][ni][3] + b1;
            c[mi][ni][0] = x0; c[mi][ni][1] = x1;
            c[mi][ni][2] = x2; c[mi][ni][3] = x3;
            sA += x0 + x1; qA = fmaf(x0, x0, fmaf(x1, x1, qA));
            sB += x2 + x3; qB = fmaf(x2, x2, fmaf(x3, x3, qB));
        }
#pragma unroll
        for (int o = 1; o <= 2; o <<= 1) {
            sA += __shfl_xor_sync(0xffffffffu, sA, o);
            qA += __shfl_xor_sync(0xffffffffu, qA, o);
            sB += __shfl_xor_sync(0xffffffffu, sB, o);
            qB += __shfl_xor_sync(0xffffffffu, qB, o);
        }
        if (tig == 0) {
            int rl = warpM * 32 + mi * 16 + g;
            redS[warpN][rl] = sA;     redQ[warpN][rl] = qA;
            redS[warpN][rl + 8] = sB; redQ[warpN][rl + 8] = qB;
        }
    }
    __syncthreads();
#pragma unroll
    for (int mi = 0; mi < 2; mi++) {
        int rlA = warpM * 32 + mi * 16 + g;
        int rlB = rlA + 8;
        float sumA = redS[0][rlA] + redS[1][rlA] + redS[2][rlA] + redS[3][rlA];
        float sqA  = redQ[0][rlA] + redQ[1][rlA] + redQ[2][rlA] + redQ[3][rlA];
        float sumB = redS[0][rlB] + redS[1][rlB] + redS[2][rlB] + redS[3][rlB];
        float sqB  = redQ[0][rlB] + redQ[1][rlB] + redQ[2][rlB] + redQ[3][rlB];
        float muA = sumA * (1.f/512.f);
        float invA = rsqrtf(sqA * (1.f/512.f) - muA*muA + 1e-5f);
        float muB = sumB * (1.f/512.f);
        float invB = rsqrtf(sqB * (1.f/512.f) - muB*muB + 1e-5f);
#pragma unroll
        for (int ni = 0; ni < 16; ni++) {
            int col = warpN * 128 + ni * 8 + kc;
            float g0 = gamma[col], g1 = gamma[col + 1];
            float e0 = beta[col],  e1 = beta[col + 1];
            float2 vA = make_float2((c[mi][ni][0] - muA) * invA * g0 + e0,
                                    (c[mi][ni][1] - muA) * invA * g1 + e1);
            float2 vB = make_float2((c[mi][ni][2] - muB) * invB * g0 + e0,
                                    (c[mi][ni][3] - muB) * invB * g1 + e1);
            *(float2*)&Y[(size_t)(row0 + rlA) * MM + col] = vA;
            *(float2*)&Y[(size_t)(row0 + rlB) * MM + col] = vB;
        }
    }
}

// =====================================================================
extern "C" void kernel_launch(void* const* d_in, const int* in_sizes, int n_in,
                              void* d_out, int out_size)
{
    const float* Q_in  = (const float*)d_in[0];
    const float* KV_in = (const float*)d_in[1];
    const float* Wq    = (const float*)d_in[2];
    const float* bq    = (const float*)d_in[3];
    const float* Wk    = (const float*)d_in[4];
    const float* bk    = (const float*)d_in[5];
    const float* Wv    = (const float*)d_in[6];
    const float* bv    = (const float*)d_in[7];
    const float* Wo    = (const float*)d_in[8];
    const float* bo    = (const float*)d_in[9];
    const float* Wqo   = (const float*)d_in[10];
    const float* bqo   = (const float*)d_in[11];
    const float* gamma = (const float*)d_in[12];
    const float* beta  = (const float*)d_in[13];
    float* out = (float*)d_out;

    const long long y_elems = (long long)NR * MM;
    const long long a_elems = (long long)BB * HH * DK * DK;
    float* attn_out = ((long long)out_size >= y_elems + a_elems) ? (out + y_elems) : nullptr;

    const int SMQ = 2 * 40960;   // 80 KB
    const int SMF = 2 * 55296;   // 108 KB
    cudaFuncSetAttribute(k_qkv_mma,  cudaFuncAttributeMaxDynamicSharedMemorySize, SMQ);
    cudaFuncSetAttribute(k_fgemm_ln, cudaFuncAttributeMaxDynamicSharedMemorySize, SMF);

    k_prep<<<1024, 256>>>(Wq, Wk, Wv, Wqo);
    k_qkv_mma<<<dim3(NR/128, 3), 256, SMQ>>>(Q_in, KV_in, bq, bk, bv);
    k_scores<<<dim3(NCHUNK, BB*HH), 256>>>();
    k_softmax<<<BB*HH, 1024>>>(attn_out);
    k_woeff<<<dim3(MM/32, BB), 256>>>(Wo);
    k_fgemm_ln<<<NR/64, 256, SMF>>>(bqo, bo, gamma, beta, out);
}

// round 16
// speedup vs baseline: 1.2872x; 1.2872x over previous
#include <cuda_runtime.h>
#include <cuda_bf16.h>
#include <cuda_fp16.h>
#include <cstdint>
#include <math.h>

// ---------------- problem constants ----------------
#define BB   16
#define LL   4096
#define NR   (BB*LL)      // 65536 rows
#define DD   512
#define CC   128
#define HH   4
#define DK   32
#define MM   512
#define NCHUNK 32
#define SCALE_F 0.17677669529663687f

// ---------------- device scratch ----------------
__device__ unsigned g_Qm[(size_t)NR * CC];
__device__ unsigned g_Km[(size_t)NR * CC];
__device__ unsigned g_Vm[(size_t)NR * CC];
__device__ float    g_part[(size_t)NCHUNK * BB * HH * DK * DK];
__device__ float    g_attn[BB * HH * DK * DK];
// transposed + split weights: [n][k] layout, k contiguous
__device__ unsigned short g_WqT_hi [128 * 512], g_WqT_lo [128 * 512];
__device__ unsigned short g_WkvT_hi[256 * 512], g_WkvT_lo[256 * 512];
// final-GEMM weights in fp16 (single-term MMA path)
__device__ __half g_WqoT_f16[512 * 128];
__device__ __half g_WoT_f16 [16 * 512 * 128];

// ---------------- helpers ----------------
__device__ __forceinline__ void split2(float x, unsigned short& h, unsigned short& l)
{
    __nv_bfloat16 hb = __float2bfloat16(x);
    float r = x - __bfloat162float(hb);
    __nv_bfloat16 lb = __float2bfloat16(r);
    h = __bfloat16_as_ushort(hb);
    l = __bfloat16_as_ushort(lb);
}
__device__ __forceinline__ unsigned packf(float x)
{
    unsigned short h, l; split2(x, h, l);
    return (unsigned)h | ((unsigned)l << 16);
}
__device__ __forceinline__ float unpackf(unsigned u)
{
    float h = __bfloat162float(__ushort_as_bfloat16((unsigned short)(u & 0xffffu)));
    float l = __bfloat162float(__ushort_as_bfloat16((unsigned short)(u >> 16)));
    return h + l;
}
__device__ __forceinline__ void mma16816(float* c, const unsigned* a, const unsigned* b)
{
    asm volatile(
        "mma.sync.aligned.m16n8k16.row.col.f32.bf16.bf16.f32 "
        "{%0,%1,%2,%3}, {%4,%5,%6,%7}, {%8,%9}, {%0,%1,%2,%3};"
        : "+f"(c[0]), "+f"(c[1]), "+f"(c[2]), "+f"(c[3])
        : "r"(a[0]), "r"(a[1]), "r"(a[2]), "r"(a[3]), "r"(b[0]), "r"(b[1]));
}
__device__ __forceinline__ void mma16816h(float* c, const unsigned* a, const unsigned* b)
{
    asm volatile(
        "mma.sync.aligned.m16n8k16.row.col.f32.f16.f16.f32 "
        "{%0,%1,%2,%3}, {%4,%5,%6,%7}, {%8,%9}, {%0,%1,%2,%3};"
        : "+f"(c[0]), "+f"(c[1]), "+f"(c[2]), "+f"(c[3])
        : "r"(a[0]), "r"(a[1]), "r"(a[2]), "r"(a[3]), "r"(b[0]), "r"(b[1]));
}
__device__ __forceinline__ uint32_t smem_u32(const void* p)
{
    uint32_t a;
    asm("{ .reg .u64 t; cvta.to.shared.u64 t, %1; cvt.u32.u64 %0, t; }" : "=r"(a) : "l"(p));
    return a;
}
__device__ __forceinline__ void ldsm4(uint32_t* r, uint32_t a)
{
    asm volatile("ldmatrix.sync.aligned.m8n8.x4.shared.b16 {%0,%1,%2,%3}, [%4];"
        : "=r"(r[0]), "=r"(r[1]), "=r"(r[2]), "=r"(r[3]) : "r"(a));
}

// =====================================================================
// k_prep: bf16-split transposed copies for QKV; fp16 copy for Wqo.
// =====================================================================
__global__ void __launch_bounds__(256) k_prep(
    const float* __restrict__ Wq, const float* __restrict__ Wk,
    const float* __restrict__ Wv, const float* __restrict__ Wqo)
{
    int e = blockIdx.x * 256 + threadIdx.x;      // 0..262143
    unsigned short h, l;
    if (e < 65536) {                              // WqT [128][512]
        int n = e >> 9, k = e & 511;
        split2(Wq[(size_t)k * 128 + n], h, l);
        g_WqT_hi[(size_t)n * 512 + k] = h; g_WqT_lo[(size_t)n * 512 + k] = l;
    } else if (e < 196608) {                      // WkvT [256][512]
        int e2 = e - 65536;
        int n = e2 >> 9, k = e2 & 511;
        float v = (n < 128) ? Wk[(size_t)k * 128 + n] : Wv[(size_t)k * 128 + (n - 128)];
        split2(v, h, l);
        g_WkvT_hi[(size_t)n * 512 + k] = h; g_WkvT_lo[(size_t)n * 512 + k] = l;
    } else {                                      // WqoT_f16 [512][128]
        int e2 = e - 196608;
        int n = e2 >> 7, k = e2 & 127;
        g_WqoT_f16[(size_t)n * 128 + k] = __float2half(Wqo[(size_t)k * 512 + n]);
    }
}

// =====================================================================
// K1: QKV projection (Round-10 winner, sync loads). grid (NR/128, 3).
// 8 warps 4Mx2N, warp 32x64, BK=32. Row stride 80B. 2 bufs x 40KB.
// =====================================================================
__global__ void __launch_bounds__(256) k_qkv_mma(
    const float* __restrict__ Q_in, const float* __restrict__ KV_in,
    const float* __restrict__ bq, const float* __restrict__ bk,
    const float* __restrict__ bv)
{
    extern __shared__ __align__(16) char smem[];
    const int t = threadIdx.x;
    const int lane = t & 31, wid = t >> 5;
    const int g = lane >> 2, tig = lane & 3;
    const int warpM = wid & 3, warpN = wid >> 2;
    const int row0 = blockIdx.x * 128;
    const int y = blockIdx.y;
    const uint32_t sb = smem_u32(smem);

    const float* A = (y == 0) ? Q_in : KV_in;
    const unsigned short* WT_hi = (y == 0) ? g_WqT_hi : (g_WkvT_hi + (size_t)(y - 1) * 128 * 512);
    const unsigned short* WT_lo = (y == 0) ? g_WqT_lo : (g_WkvT_lo + (size_t)(y - 1) * 128 * 512);
    const float* bias = (y == 0) ? bq : ((y == 1) ? bk : bv);
    unsigned* outp = (y == 0) ? g_Qm : ((y == 1) ? g_Km : g_Vm);

    const uint32_t BUF = 40960;
    const uint32_t aoff = (uint32_t)((warpM * 32 + (lane & 7) + ((lane >> 3) & 1) * 8) * 80
                                     + ((lane >> 4) & 1) * 16);
    const uint32_t boff = (uint32_t)((warpN * 64 + (lane & 7) + ((lane >> 4) & 1) * 8) * 80
                                     + ((lane >> 3) & 1) * 16);

    float c[2][8][4];
#pragma unroll
    for (int mi = 0; mi < 2; mi++)
#pragma unroll
        for (int ni = 0; ni < 8; ni++)
#pragma unroll
            for (int q = 0; q < 4; q++) c[mi][ni][q] = 0.f;

    float4 av[4];
    uint4 bh4[2], bl4[2];

    auto gload = [&](int cc) {
        const int kk = cc * 32;
#pragma unroll
        for (int i = 0; i < 4; i++) {
            int f = i * 256 + t, r = f >> 3, kq = (f & 7) * 4;
            av[i] = *(const float4*)(A + (size_t)(row0 + r) * DD + kk + kq);
        }
#pragma unroll
        for (int i = 0; i < 2; i++) {
            int f = i * 256 + t, n = f >> 2, k8 = (f & 3) * 8;
            size_t idx = (size_t)n * DD + kk + k8;
            bh4[i] = *(const uint4*)(WT_hi + idx);
            bl4[i] = *(const uint4*)(WT_lo + idx);
        }
    };
    auto sstore = [&](int buf) {
        char* b0 = smem + buf * BUF;
#pragma unroll
        for (int i = 0; i < 4; i++) {
            int f = i * 256 + t, r = f >> 3, kq = (f & 7) * 4;
            unsigned short h0,h1,h2,h3,l0,l1,l2,l3;
            split2(av[i].x, h0, l0); split2(av[i].y, h1, l1);
            split2(av[i].z, h2, l2); split2(av[i].w, h3, l3);
            int off = r * 80 + kq * 2;
            *(uint2*)(b0 + off) = make_uint2((unsigned)h0 | ((unsigned)h1 << 16),
                                             (unsigned)h2 | ((unsigned)h3 << 16));
            *(uint2*)(b0 + 10240 + off) = make_uint2((unsigned)l0 | ((unsigned)l1 << 16),
                                                     (unsigned)l2 | ((unsigned)l3 << 16));
        }
#pragma unroll
        for (int i = 0; i < 2; i++) {
            int f = i * 256 + t, n = f >> 2, k8 = (f & 3) * 8;
            int off = n * 80 + k8 * 2;
            *(uint4*)(b0 + 20480 + off) = bh4[i];
            *(uint4*)(b0 + 30720 + off) = bl4[i];
        }
    };
    auto compute = [&](int buf) {
        const uint32_t base = sb + buf * BUF;
#pragma unroll
        for (int ks = 0; ks < 2; ks++) {
            const uint32_t ko = ks * 32;
            uint32_t ah[2][4], al[2][4];
            ldsm4(ah[0], base + aoff + ko);
            ldsm4(ah[1], base + aoff + 1280 + ko);
            ldsm4(al[0], base + 10240 + aoff + ko);
            ldsm4(al[1], base + 10240 + aoff + 1280 + ko);
#pragma unroll
            for (int p = 0; p < 4; p++) {
                uint32_t bh[4], bl[4];
                ldsm4(bh, base + 20480 + boff + p * 1280 + ko);
                ldsm4(bl, base + 30720 + boff + p * 1280 + ko);
#pragma unroll
                for (int q = 0; q < 2; q++)
#pragma unroll
                    for (int mi = 0; mi < 2; mi++) {
                        mma16816(c[mi][2*p+q], ah[mi], bh + 2*q);
                        mma16816(c[mi][2*p+q], ah[mi], bl + 2*q);
                        mma16816(c[mi][2*p+q], al[mi], bh + 2*q);
                    }
            }
        }
    };

    gload(0);
    sstore(0);
    __syncthreads();
#pragma unroll 1
    for (int cc = 0; cc < 16; cc++) {
        const int buf = cc & 1;
        if (cc < 15) gload(cc + 1);
        compute(buf);
        if (cc < 15) {
            sstore(buf ^ 1);
            __syncthreads();
        }
    }

#pragma unroll
    for (int mi = 0; mi < 2; mi++) {
        int r0 = row0 + warpM * 32 + mi * 16 + g;
#pragma unroll
        for (int ni = 0; ni < 8; ni++) {
            int col = warpN * 64 + ni * 8 + tig * 2;
            float b0f = bias[col], b1f = bias[col + 1];
            unsigned p00 = packf(c[mi][ni][0] + b0f);
            unsigned p01 = packf(c[mi][ni][1] + b1f);
            unsigned p10 = packf(c[mi][ni][2] + b0f);
            unsigned p11 = packf(c[mi][ni][3] + b1f);
            *(uint2*)&outp[(size_t)r0 * CC + col]       = make_uint2(p00, p01);
            *(uint2*)&outp[(size_t)(r0 + 8) * CC + col] = make_uint2(p10, p11);
        }
    }
}

// =====================================================================
// K2: partial scores (reads packed Qm/Km).
// =====================================================================
__global__ void __launch_bounds__(256) k_scores()
{
    __shared__ float Qs[128][32];
    __shared__ float Ks[128][32];
    const int t = threadIdx.x;
    const int chunk = blockIdx.x;
    const int bh = blockIdx.y;
    const int b = bh >> 2, h = bh & 3;
    const int rowbase = b * LL + chunk * 128;

#pragma unroll
    for (int i = 0; i < 4; i++) {
        int f = i * 256 + t;
        int r = f >> 3, j = (f & 7) * 4;
        uint4 q = *(const uint4*)(g_Qm + (size_t)(rowbase + r) * CC + h * DK + j);
        uint4 k = *(const uint4*)(g_Km + (size_t)(rowbase + r) * CC + h * DK + j);
        Qs[r][j+0] = unpackf(q.x); Qs[r][j+1] = unpackf(q.y);
        Qs[r][j+2] = unpackf(q.z); Qs[r][j+3] = unpackf(q.w);
        Ks[r][j+0] = unpackf(k.x); Ks[r][j+1] = unpackf(k.y);
        Ks[r][j+2] = unpackf(k.z); Ks[r][j+3] = unpackf(k.w);
    }
    __syncthreads();

    const int tile = t & 63, ly = t >> 6;
    const int d0 = (tile >> 3) * 4, e0 = (tile & 7) * 4;
    float acc[4][4];
#pragma unroll
    for (int r = 0; r < 4; r++)
#pragma unroll
        for (int c = 0; c < 4; c++) acc[r][c] = 0.f;

    for (int l = ly; l < 128; l += 4) {
        float4 q = *(const float4*)&Qs[l][d0];
        float4 k = *(const float4*)&Ks[l][e0];
        float qa[4] = {q.x,q.y,q.z,q.w};
        float ka[4] = {k.x,k.y,k.z,k.w};
#pragma unroll
        for (int r = 0; r < 4; r++)
#pragma unroll
            for (int c = 0; c < 4; c++)
                acc[r][c] = fmaf(qa[r], ka[c], acc[r][c]);
    }
    __syncthreads();
    float* red = &Qs[0][0];
#pragma unroll
    for (int r = 0; r < 4; r++)
#pragma unroll
        for (int c = 0; c < 4; c++) red[t*16 + r*4 + c] = acc[r][c];
    __syncthreads();
    if (t < 64) {
        const int dd0 = (t >> 3) * 4, ee0 = (t & 7) * 4;
#pragma unroll
        for (int i = 0; i < 16; i++) {
            float s = red[t*16+i] + red[(t+64)*16+i] + red[(t+128)*16+i] + red[(t+192)*16+i];
            int r = i >> 2, c = i & 3;
            g_part[(size_t)chunk * 65536 + bh*1024 + (dd0+r)*32 + (ee0+c)] = s;
        }
    }
}

// =====================================================================
// K3: reduce + softmax.
// =====================================================================
__global__ void __launch_bounds__(1024) k_softmax(float* __restrict__ attn_out)
{
    const int bh = blockIdx.x;
    const int t = threadIdx.x;
    float s = 0.f;
#pragma unroll
    for (int c = 0; c < NCHUNK; c++) s += g_part[(size_t)c*65536 + bh*1024 + t];
    s *= SCALE_F;
    float m = s;
#pragma unroll
    for (int o = 16; o; o >>= 1) m = fmaxf(m, __shfl_xor_sync(0xffffffffu, m, o));
    float ex = expf(s - m);
    float sum = ex;
#pragma unroll
    for (int o = 16; o; o >>= 1) sum += __shfl_xor_sync(0xffffffffu, sum, o);
    float a = ex / sum;
    g_attn[bh*1024 + t] = a;
    if (attn_out) attn_out[bh*1024 + t] = a;
}

// =====================================================================
// K4: WoEff transposed, fp16: g_WoT_f16[b][m][e] = sum_d attn*Wo.
// =====================================================================
__global__ void __launch_bounds__(256) k_woeff(const float* __restrict__ Wo)
{
    __shared__ float at[4096];
    __shared__ float wo_s[128][32];
    const int m0 = blockIdx.x * 32;
    const int b  = blockIdx.y;
    const int t  = threadIdx.x;
#pragma unroll
    for (int i = 0; i < 4; i++) {
        int f = i*256 + t;
        *(float4*)&at[f*4] = *(const float4*)(g_attn + (size_t)b*4096 + f*4);
    }
#pragma unroll
    for (int i = 0; i < 4; i++) {
        int f = i*256 + t;
        int r = f >> 3, c = (f & 7) * 4;
        *(float4*)&wo_s[r][c] = *(const float4*)(Wo + (size_t)r*MM + m0 + c);
    }
    __syncthreads();
    const int tx = t & 31, ty = t >> 5;
#pragma unroll
    for (int i = 0; i < 16; i++) {
        int he = ty + 8*i;
        int h = he >> 5, e = he & 31;
        float s = 0.f;
#pragma unroll
        for (int d = 0; d < 32; d++)
            s = fmaf(at[h*1024 + d*32 + e], wo_s[h*32+d][tx], s);
        size_t o = ((size_t)b * 512 + (m0 + tx)) * 128 + he;
        g_WoT_f16[o] = __float2half(s);
    }
}

// =====================================================================
// K5: fused final GEMM + LN, SINGLE-TERM fp16 MMA.
// 256 threads, 8 warps 2Mx4N, BM=64, BN=512, BK=16, warp 32x128.
// Per buffer: A fp16 @0 (64x48B=3072), B fp16 @3072 (512x48B=24576).
// Dyn smem 2 x 27648 = 55296.
// =====================================================================
__global__ void __launch_bounds__(256) k_fgemm_ln(
    const float* __restrict__ bqo, const float* __restrict__ bo,
    const float* __restrict__ gamma, const float* __restrict__ beta,
    float* __restrict__ Y)
{
    extern __shared__ __align__(16) char smem[];
    __shared__ float redS[4][64], redQ[4][64];

    const int t = threadIdx.x;
    const int lane = t & 31, wid = t >> 5;
    const int g = lane >> 2, tig = lane & 3;
    const int warpM = wid & 1, warpN = wid >> 1;   // 2M x 4N
    const int row0 = blockIdx.x * 64;
    const int b = row0 >> 12;
    const int kc = tig * 2;
    const uint32_t sb = smem_u32(smem);

    const uint32_t BUF = 27648;
    const uint32_t aoff = (uint32_t)((warpM * 32 + (lane & 7) + ((lane >> 3) & 1) * 8) * 48
                                     + ((lane >> 4) & 1) * 16);
    const uint32_t boff = (uint32_t)((warpN * 128 + (lane & 7) + ((lane >> 4) & 1) * 8) * 48
                                     + ((lane >> 3) & 1) * 16);

    float c[2][16][4];
#pragma unroll
    for (int mi = 0; mi < 2; mi++)
#pragma unroll
        for (int ni = 0; ni < 16; ni++)
#pragma unroll
            for (int q = 0; q < 4; q++) c[mi][ni][q] = 0.f;

    uint4 av;
    uint4 b4[4];

    auto gload = [&](int cc) {
        const int kk = cc * 16;
        {
            int r = t >> 2, kq = (t & 3) * 4;
            int kg = kk + kq;
            const unsigned* src = (kk < 128)
                ? (g_Qm + (size_t)(row0 + r) * CC + kg)
                : (g_Vm + (size_t)(row0 + r) * CC + (kg - 128));
            av = *(const uint4*)src;
        }
        // B: 512 rows x 16 k fp16 = 1024 uint4, 4 per thread
#pragma unroll
        for (int i = 0; i < 4; i++) {
            int f = i * 256 + t;
            int n = f >> 1, k8 = (f & 1) * 8;
            const __half* src;
            if (kk < 128) src = g_WqoT_f16 + (size_t)n * 128 + kk + k8;
            else          src = g_WoT_f16 + ((size_t)b * 512 + n) * 128 + (kk - 128) + k8;
            b4[i] = *(const uint4*)src;
        }
    };
    auto sstore = [&](int buf) {
        char* b0 = smem + buf * BUF;
        {
            int r = t >> 2, kq = (t & 3) * 4;
            float f0 = unpackf(av.x), f1 = unpackf(av.y);
            float f2 = unpackf(av.z), f3 = unpackf(av.w);
            __half2 h01 = __floats2half2_rn(f0, f1);
            __half2 h23 = __floats2half2_rn(f2, f3);
            int off = r * 48 + kq * 2;
            *(uint2*)(b0 + off) = make_uint2(*(unsigned*)&h01, *(unsigned*)&h23);
        }
#pragma unroll
        for (int i = 0; i < 4; i++) {
            int f = i * 256 + t;
            int n = f >> 1, k8 = (f & 1) * 8;
            int off = n * 48 + k8 * 2;
            *(uint4*)(b0 + 3072 + off) = b4[i];
        }
    };
    auto compute = [&](int buf) {
        const uint32_t base = sb + buf * BUF;
        uint32_t a[2][4];
        ldsm4(a[0], base + aoff);
        ldsm4(a[1], base + aoff + 768);
#pragma unroll
        for (int p = 0; p < 8; p++) {
            uint32_t bh[4];
            ldsm4(bh, base + 3072 + boff + p * 768);
#pragma unroll
            for (int q = 0; q < 2; q++)
#pragma unroll
                for (int mi = 0; mi < 2; mi++)
                    mma16816h(c[mi][2*p+q], a[mi], bh + 2*q);
        }
    };

    gload(0);
    sstore(0);
    __syncthreads();
#pragma unroll 1
    for (int cc = 0; cc < 16; cc++) {
        const int buf = cc & 1;
        if (cc < 15) gload(cc + 1);
        compute(buf);
        if (cc < 15) {
            sstore(buf ^ 1);
            __syncthreads();
        }
    }

    // ---- epilogue: bias, LN stats, normalize, store ----
#pragma unroll
    for (int mi = 0; mi < 2; mi++) {
        float sA = 0.f, qA = 0.f, sB = 0.f, qB = 0.f;
#pragma unroll
        for (int ni = 0; ni < 16; ni++) {
            int col = warpN * 128 + ni * 8 + kc;
            float b0 = bqo[col] + bo[col];
            float b1 = bqo[col + 1] + bo[col + 1];
            float x0 = c[mi][ni][0] + b0, x1 = c[mi][ni][1] + b1;
            float x2 = c[mi][ni][2] + b0, x3 = c[mi][ni][3] + b1;
            c[mi][ni][0] = x0; c[mi][ni][1] = x1;
            c[mi][ni][2] = x2; c[mi][ni][3] = x3;
            sA += x0 + x1; qA = fmaf(x0, x0, fmaf(x1, x1, qA));
            sB += x2 + x3; qB = fmaf(x2, x2, fmaf(x3, x3, qB));
        }
#pragma unroll
        for (int o = 1; o <= 2; o <<= 1) {
            sA += __shfl_xor_sync(0xffffffffu, sA, o);
            qA += __shfl_xor_sync(0xffffffffu, qA, o);
            sB += __shfl_xor_sync(0xffffffffu, sB, o);
            qB += __shfl_xor_sync(0xffffffffu, qB, o);
        }
        if (tig == 0) {
            int rl = warpM * 32 + mi * 16 + g;
            redS[warpN][rl] = sA;     redQ[warpN][rl] = qA;
            redS[warpN][rl + 8] = sB; redQ[warpN][rl + 8] = qB;
        }
    }
    __syncthreads();
#pragma unroll
    for (int mi = 0; mi < 2; mi++) {
        int rlA = warpM * 32 + mi * 16 + g;
        int rlB = rlA + 8;
        float sumA = redS[0][rlA] + redS[1][rlA] + redS[2][rlA] + redS[3][rlA];
        float sqA  = redQ[0][rlA] + redQ[1][rlA] + redQ[2][rlA] + redQ[3][rlA];
        float sumB = redS[0][rlB] + redS[1][rlB] + redS[2][rlB] + redS[3][rlB];
        float sqB  = redQ[0][rlB] + redQ[1][rlB] + redQ[2][rlB] + redQ[3][rlB];
        float muA = sumA * (1.f/512.f);
        float invA = rsqrtf(sqA * (1.f/512.f) - muA*muA + 1e-5f);
        float muB = sumB * (1.f/512.f);
        float invB = rsqrtf(sqB * (1.f/512.f) - muB*muB + 1e-5f);
#pragma unroll
        for (int ni = 0; ni < 16; ni++) {
            int col = warpN * 128 + ni * 8 + kc;
            float g0 = gamma[col], g1 = gamma[col + 1];
            float e0 = beta[col],  e1 = beta[col + 1];
            float2 vA = make_float2((c[mi][ni][0] - muA) * invA * g0 + e0,
                                    (c[mi][ni][1] - muA) * invA * g1 + e1);
            float2 vB = make_float2((c[mi][ni][2] - muB) * invB * g0 + e0,
                                    (c[mi][ni][3] - muB) * invB * g1 + e1);
            *(float2*)&Y[(size_t)(row0 + rlA) * MM + col] = vA;
            *(float2*)&Y[(size_t)(row0 + rlB) * MM + col] = vB;
        }
    }
}

// =====================================================================
extern "C" void kernel_launch(void* const* d_in, const int* in_sizes, int n_in,
                              void* d_out, int out_size)
{
    const float* Q_in  = (const float*)d_in[0];
    const float* KV_in = (const float*)d_in[1];
    const float* Wq    = (const float*)d_in[2];
    const float* bq    = (const float*)d_in[3];
    const float* Wk    = (const float*)d_in[4];
    const float* bk    = (const float*)d_in[5];
    const float* Wv    = (const float*)d_in[6];
    const float* bv    = (const float*)d_in[7];
    const float* Wo    = (const float*)d_in[8];
    const float* bo    = (const float*)d_in[9];
    const float* Wqo   = (const float*)d_in[10];
    const float* bqo   = (const float*)d_in[11];
    const float* gamma = (const float*)d_in[12];
    const float* beta  = (const float*)d_in[13];
    float* out = (float*)d_out;

    const long long y_elems = (long long)NR * MM;
    const long long a_elems = (long long)BB * HH * DK * DK;
    float* attn_out = ((long long)out_size >= y_elems + a_elems) ? (out + y_elems) : nullptr;

    const int SMQ = 2 * 40960;   // 80 KB
    const int SMF = 2 * 27648;   // 54 KB
    cudaFuncSetAttribute(k_qkv_mma,  cudaFuncAttributeMaxDynamicSharedMemorySize, SMQ);
    cudaFuncSetAttribute(k_fgemm_ln, cudaFuncAttributeMaxDynamicSharedMemorySize, SMF);

    k_prep<<<1024, 256>>>(Wq, Wk, Wv, Wqo);
    k_qkv_mma<<<dim3(NR/128, 3), 256, SMQ>>>(Q_in, KV_in, bq, bk, bv);
    k_scores<<<dim3(NCHUNK, BB*HH), 256>>>();
    k_softmax<<<BB*HH, 1024>>>(attn_out);
    k_woeff<<<dim3(MM/32, BB), 256>>>(Wo);
    k_fgemm_ln<<<NR/64, 256, SMF>>>(bqo, bo, gamma, beta, out);
}

// round 17
// speedup vs baseline: 1.5600x; 1.2119x over previous
#include <cuda_runtime.h>
#include <cuda_bf16.h>
#include <cuda_fp16.h>
#include <cstdint>
#include <math.h>

// ---------------- problem constants ----------------
#define BB   16
#define LL   4096
#define NR   (BB*LL)      // 65536 rows
#define DD   512
#define CC   128
#define HH   4
#define DK   32
#define MM   512
#define NCHUNK 32
#define SCALE_F 0.17677669529663687f

// ---------------- device scratch ----------------
__device__ unsigned g_Qm[(size_t)NR * CC];     // packed bf16 hi|lo of fp32 result
__device__ unsigned g_Km[(size_t)NR * CC];
__device__ unsigned g_Vm[(size_t)NR * CC];
__device__ float    g_part[(size_t)NCHUNK * BB * HH * DK * DK];
__device__ float    g_attn[BB * HH * DK * DK];
// QKV weights: transposed fp16 2-term split [n][k]
__device__ __half g_WqT_h [128 * 512], g_WqT_l [128 * 512];
__device__ __half g_WkvT_h[256 * 512], g_WkvT_l[256 * 512];
// final-GEMM weights in fp16 (single-term MMA path)
__device__ __half g_WqoT_f16[512 * 128];
__device__ __half g_WoT_f16 [16 * 512 * 128];

// ---------------- helpers ----------------
__device__ __forceinline__ void split2(float x, unsigned short& h, unsigned short& l)
{
    __nv_bfloat16 hb = __float2bfloat16(x);
    float r = x - __bfloat162float(hb);
    __nv_bfloat16 lb = __float2bfloat16(r);
    h = __bfloat16_as_ushort(hb);
    l = __bfloat16_as_ushort(lb);
}
__device__ __forceinline__ unsigned packf(float x)
{
    unsigned short h, l; split2(x, h, l);
    return (unsigned)h | ((unsigned)l << 16);
}
__device__ __forceinline__ float unpackf(unsigned u)
{
    float h = __bfloat162float(__ushort_as_bfloat16((unsigned short)(u & 0xffffu)));
    float l = __bfloat162float(__ushort_as_bfloat16((unsigned short)(u >> 16)));
    return h + l;
}
__device__ __forceinline__ void split2h(float x, __half& h, __half& l)
{
    h = __float2half(x);
    l = __float2half(x - __half2float(h));
}
__device__ __forceinline__ void mma16816h(float* c, const unsigned* a, const unsigned* b)
{
    asm volatile(
        "mma.sync.aligned.m16n8k16.row.col.f32.f16.f16.f32 "
        "{%0,%1,%2,%3}, {%4,%5,%6,%7}, {%8,%9}, {%0,%1,%2,%3};"
        : "+f"(c[0]), "+f"(c[1]), "+f"(c[2]), "+f"(c[3])
        : "r"(a[0]), "r"(a[1]), "r"(a[2]), "r"(a[3]), "r"(b[0]), "r"(b[1]));
}
__device__ __forceinline__ uint32_t smem_u32(const void* p)
{
    uint32_t a;
    asm("{ .reg .u64 t; cvta.to.shared.u64 t, %1; cvt.u32.u64 %0, t; }" : "=r"(a) : "l"(p));
    return a;
}
__device__ __forceinline__ void ldsm4(uint32_t* r, uint32_t a)
{
    asm volatile("ldmatrix.sync.aligned.m8n8.x4.shared.b16 {%0,%1,%2,%3}, [%4];"
        : "=r"(r[0]), "=r"(r[1]), "=r"(r[2]), "=r"(r[3]) : "r"(a));
}

// =====================================================================
// k_prep: fp16-split transposed copies for QKV; fp16 copy for Wqo.
// =====================================================================
__global__ void __launch_bounds__(256) k_prep(
    const float* __restrict__ Wq, const float* __restrict__ Wk,
    const float* __restrict__ Wv, const float* __restrict__ Wqo)
{
    int e = blockIdx.x * 256 + threadIdx.x;      // 0..262143
    __half h, l;
    if (e < 65536) {                              // WqT [128][512]
        int n = e >> 9, k = e & 511;
        split2h(Wq[(size_t)k * 128 + n], h, l);
        g_WqT_h[(size_t)n * 512 + k] = h; g_WqT_l[(size_t)n * 512 + k] = l;
    } else if (e < 196608) {                      // WkvT [256][512]
        int e2 = e - 65536;
        int n = e2 >> 9, k = e2 & 511;
        float v = (n < 128) ? Wk[(size_t)k * 128 + n] : Wv[(size_t)k * 128 + (n - 128)];
        split2h(v, h, l);
        g_WkvT_h[(size_t)n * 512 + k] = h; g_WkvT_l[(size_t)n * 512 + k] = l;
    } else {                                      // WqoT_f16 [512][128]
        int e2 = e - 196608;
        int n = e2 >> 7, k = e2 & 127;
        g_WqoT_f16[(size_t)n * 128 + k] = __float2half(Wqo[(size_t)k * 512 + n]);
    }
}

// =====================================================================
// K1: QKV projection, 2-term fp16 MMA: a_f16 * (wh + wl).
// grid (NR/128, 3): y=0 Qm, y=1 Km, y=2 Vm. 8 warps 4Mx2N, warp 32x64,
// BK=32. Per buffer: A fp16 @0 (10240), Bh @10240, Bl @20480. 2 x 30KB.
// =====================================================================
__global__ void __launch_bounds__(256) k_qkv_mma(
    const float* __restrict__ Q_in, const float* __restrict__ KV_in,
    const float* __restrict__ bq, const float* __restrict__ bk,
    const float* __restrict__ bv)
{
    extern __shared__ __align__(16) char smem[];
    const int t = threadIdx.x;
    const int lane = t & 31, wid = t >> 5;
    const int g = lane >> 2, tig = lane & 3;
    const int warpM = wid & 3, warpN = wid >> 2;
    const int row0 = blockIdx.x * 128;
    const int y = blockIdx.y;
    const uint32_t sb = smem_u32(smem);

    const float* A = (y == 0) ? Q_in : KV_in;
    const __half* WT_h = (y == 0) ? g_WqT_h : (g_WkvT_h + (size_t)(y - 1) * 128 * 512);
    const __half* WT_l = (y == 0) ? g_WqT_l : (g_WkvT_l + (size_t)(y - 1) * 128 * 512);
    const float* bias = (y == 0) ? bq : ((y == 1) ? bk : bv);
    unsigned* outp = (y == 0) ? g_Qm : ((y == 1) ? g_Km : g_Vm);

    const uint32_t BUF = 30720;
    const uint32_t aoff = (uint32_t)((warpM * 32 + (lane & 7) + ((lane >> 3) & 1) * 8) * 80
                                     + ((lane >> 4) & 1) * 16);
    const uint32_t boff = (uint32_t)((warpN * 64 + (lane & 7) + ((lane >> 4) & 1) * 8) * 80
                                     + ((lane >> 3) & 1) * 16);

    float c[2][8][4];
#pragma unroll
    for (int mi = 0; mi < 2; mi++)
#pragma unroll
        for (int ni = 0; ni < 8; ni++)
#pragma unroll
            for (int q = 0; q < 4; q++) c[mi][ni][q] = 0.f;

    float4 av[4];
    uint4 bh4[2], bl4[2];

    auto gload = [&](int cc) {
        const int kk = cc * 32;
#pragma unroll
        for (int i = 0; i < 4; i++) {
            int f = i * 256 + t, r = f >> 3, kq = (f & 7) * 4;
            av[i] = *(const float4*)(A + (size_t)(row0 + r) * DD + kk + kq);
        }
#pragma unroll
        for (int i = 0; i < 2; i++) {
            int f = i * 256 + t, n = f >> 2, k8 = (f & 3) * 8;
            size_t idx = (size_t)n * DD + kk + k8;
            bh4[i] = *(const uint4*)(WT_h + idx);
            bl4[i] = *(const uint4*)(WT_l + idx);
        }
    };
    auto sstore = [&](int buf) {
        char* b0 = smem + buf * BUF;
#pragma unroll
        for (int i = 0; i < 4; i++) {
            int f = i * 256 + t, r = f >> 3, kq = (f & 7) * 4;
            __half2 h01 = __floats2half2_rn(av[i].x, av[i].y);
            __half2 h23 = __floats2half2_rn(av[i].z, av[i].w);
            int off = r * 80 + kq * 2;
            *(uint2*)(b0 + off) = make_uint2(*(unsigned*)&h01, *(unsigned*)&h23);
        }
#pragma unroll
        for (int i = 0; i < 2; i++) {
            int f = i * 256 + t, n = f >> 2, k8 = (f & 3) * 8;
            int off = n * 80 + k8 * 2;
            *(uint4*)(b0 + 10240 + off) = bh4[i];
            *(uint4*)(b0 + 20480 + off) = bl4[i];
        }
    };
    auto compute = [&](int buf) {
        const uint32_t base = sb + buf * BUF;
#pragma unroll
        for (int ks = 0; ks < 2; ks++) {
            const uint32_t ko = ks * 32;
            uint32_t a[2][4];
            ldsm4(a[0], base + aoff + ko);
            ldsm4(a[1], base + aoff + 1280 + ko);
#pragma unroll
            for (int p = 0; p < 4; p++) {
                uint32_t bh[4], bl[4];
                ldsm4(bh, base + 10240 + boff + p * 1280 + ko);
                ldsm4(bl, base + 20480 + boff + p * 1280 + ko);
#pragma unroll
                for (int q = 0; q < 2; q++)
#pragma unroll
                    for (int mi = 0; mi < 2; mi++) {
                        mma16816h(c[mi][2*p+q], a[mi], bh + 2*q);
                        mma16816h(c[mi][2*p+q], a[mi], bl + 2*q);
                    }
            }
        }
    };

    gload(0);
    sstore(0);
    __syncthreads();
#pragma unroll 1
    for (int cc = 0; cc < 16; cc++) {
        const int buf = cc & 1;
        if (cc < 15) gload(cc + 1);
        compute(buf);
        if (cc < 15) {
            sstore(buf ^ 1);
            __syncthreads();
        }
    }

#pragma unroll
    for (int mi = 0; mi < 2; mi++) {
        int r0 = row0 + warpM * 32 + mi * 16 + g;
#pragma unroll
        for (int ni = 0; ni < 8; ni++) {
            int col = warpN * 64 + ni * 8 + tig * 2;
            float b0f = bias[col], b1f = bias[col + 1];
            unsigned p00 = packf(c[mi][ni][0] + b0f);
            unsigned p01 = packf(c[mi][ni][1] + b1f);
            unsigned p10 = packf(c[mi][ni][2] + b0f);
            unsigned p11 = packf(c[mi][ni][3] + b1f);
            *(uint2*)&outp[(size_t)r0 * CC + col]       = make_uint2(p00, p01);
            *(uint2*)&outp[(size_t)(r0 + 8) * CC + col] = make_uint2(p10, p11);
        }
    }
}

// =====================================================================
// K2: partial scores (reads packed Qm/Km).
// =====================================================================
__global__ void __launch_bounds__(256) k_scores()
{
    __shared__ float Qs[128][32];
    __shared__ float Ks[128][32];
    const int t = threadIdx.x;
    const int chunk = blockIdx.x;
    const int bh = blockIdx.y;
    const int b = bh >> 2, h = bh & 3;
    const int rowbase = b * LL + chunk * 128;

#pragma unroll
    for (int i = 0; i < 4; i++) {
        int f = i * 256 + t;
        int r = f >> 3, j = (f & 7) * 4;
        uint4 q = *(const uint4*)(g_Qm + (size_t)(rowbase + r) * CC + h * DK + j);
        uint4 k = *(const uint4*)(g_Km + (size_t)(rowbase + r) * CC + h * DK + j);
        Qs[r][j+0] = unpackf(q.x); Qs[r][j+1] = unpackf(q.y);
        Qs[r][j+2] = unpackf(q.z); Qs[r][j+3] = unpackf(q.w);
        Ks[r][j+0] = unpackf(k.x); Ks[r][j+1] = unpackf(k.y);
        Ks[r][j+2] = unpackf(k.z); Ks[r][j+3] = unpackf(k.w);
    }
    __syncthreads();

    const int tile = t & 63, ly = t >> 6;
    const int d0 = (tile >> 3) * 4, e0 = (tile & 7) * 4;
    float acc[4][4];
#pragma unroll
    for (int r = 0; r < 4; r++)
#pragma unroll
        for (int c = 0; c < 4; c++) acc[r][c] = 0.f;

    for (int l = ly; l < 128; l += 4) {
        float4 q = *(const float4*)&Qs[l][d0];
        float4 k = *(const float4*)&Ks[l][e0];
        float qa[4] = {q.x,q.y,q.z,q.w};
        float ka[4] = {k.x,k.y,k.z,k.w};
#pragma unroll
        for (int r = 0; r < 4; r++)
#pragma unroll
            for (int c = 0; c < 4; c++)
                acc[r][c] = fmaf(qa[r], ka[c], acc[r][c]);
    }
    __syncthreads();
    float* red = &Qs[0][0];
#pragma unroll
    for (int r = 0; r < 4; r++)
#pragma unroll
        for (int c = 0; c < 4; c++) red[t*16 + r*4 + c] = acc[r][c];
    __syncthreads();
    if (t < 64) {
        const int dd0 = (t >> 3) * 4, ee0 = (t & 7) * 4;
#pragma unroll
        for (int i = 0; i < 16; i++) {
            float s = red[t*16+i] + red[(t+64)*16+i] + red[(t+128)*16+i] + red[(t+192)*16+i];
            int r = i >> 2, c = i & 3;
            g_part[(size_t)chunk * 65536 + bh*1024 + (dd0+r)*32 + (ee0+c)] = s;
        }
    }
}

// =====================================================================
// K3: reduce + softmax.
// =====================================================================
__global__ void __launch_bounds__(1024) k_softmax(float* __restrict__ attn_out)
{
    const int bh = blockIdx.x;
    const int t = threadIdx.x;
    float s = 0.f;
#pragma unroll
    for (int c = 0; c < NCHUNK; c++) s += g_part[(size_t)c*65536 + bh*1024 + t];
    s *= SCALE_F;
    float m = s;
#pragma unroll
    for (int o = 16; o; o >>= 1) m = fmaxf(m, __shfl_xor_sync(0xffffffffu, m, o));
    float ex = expf(s - m);
    float sum = ex;
#pragma unroll
    for (int o = 16; o; o >>= 1) sum += __shfl_xor_sync(0xffffffffu, sum, o);
    float a = ex / sum;
    g_attn[bh*1024 + t] = a;
    if (attn_out) attn_out[bh*1024 + t] = a;
}

// =====================================================================
// K4: WoEff transposed, fp16: g_WoT_f16[b][m][e] = sum_d attn*Wo.
// =====================================================================
__global__ void __launch_bounds__(256) k_woeff(const float* __restrict__ Wo)
{
    __shared__ float at[4096];
    __shared__ float wo_s[128][32];
    const int m0 = blockIdx.x * 32;
    const int b  = blockIdx.y;
    const int t  = threadIdx.x;
#pragma unroll
    for (int i = 0; i < 4; i++) {
        int f = i*256 + t;
        *(float4*)&at[f*4] = *(const float4*)(g_attn + (size_t)b*4096 + f*4);
    }
#pragma unroll
    for (int i = 0; i < 4; i++) {
        int f = i*256 + t;
        int r = f >> 3, c = (f & 7) * 4;
        *(float4*)&wo_s[r][c] = *(const float4*)(Wo + (size_t)r*MM + m0 + c);
    }
    __syncthreads();
    const int tx = t & 31, ty = t >> 5;
#pragma unroll
    for (int i = 0; i < 16; i++) {
        int he = ty + 8*i;
        int h = he >> 5, e = he & 31;
        float s = 0.f;
#pragma unroll
        for (int d = 0; d < 32; d++)
            s = fmaf(at[h*1024 + d*32 + e], wo_s[h*32+d][tx], s);
        size_t o = ((size_t)b * 512 + (m0 + tx)) * 128 + he;
        g_WoT_f16[o] = __float2half(s);
    }
}

// =====================================================================
// K5: fused final GEMM + LN, single-term fp16 MMA (Round-16 winner).
// 256 threads, 8 warps 2Mx4N, BM=64, BN=512, BK=16, warp 32x128.
// Per buffer: A fp16 @0 (3072), B fp16 @3072 (24576). 2 x 27648.
// =====================================================================
__global__ void __launch_bounds__(256) k_fgemm_ln(
    const float* __restrict__ bqo, const float* __restrict__ bo,
    const float* __restrict__ gamma, const float* __restrict__ beta,
    float* __restrict__ Y)
{
    extern __shared__ __align__(16) char smem[];
    __shared__ float redS[4][64], redQ[4][64];

    const int t = threadIdx.x;
    const int lane = t & 31, wid = t >> 5;
    const int g = lane >> 2, tig = lane & 3;
    const int warpM = wid & 1, warpN = wid >> 1;   // 2M x 4N
    const int row0 = blockIdx.x * 64;
    const int b = row0 >> 12;
    const int kc = tig * 2;
    const uint32_t sb = smem_u32(smem);

    const uint32_t BUF = 27648;
    const uint32_t aoff = (uint32_t)((warpM * 32 + (lane & 7) + ((lane >> 3) & 1) * 8) * 48
                                     + ((lane >> 4) & 1) * 16);
    const uint32_t boff = (uint32_t)((warpN * 128 + (lane & 7) + ((lane >> 4) & 1) * 8) * 48
                                     + ((lane >> 3) & 1) * 16);

    float c[2][16][4];
#pragma unroll
    for (int mi = 0; mi < 2; mi++)
#pragma unroll
        for (int ni = 0; ni < 16; ni++)
#pragma unroll
            for (int q = 0; q < 4; q++) c[mi][ni][q] = 0.f;

    uint4 av;
    uint4 b4[4];

    auto gload = [&](int cc) {
        const int kk = cc * 16;
        {
            int r = t >> 2, kq = (t & 3) * 4;
            int kg = kk + kq;
            const unsigned* src = (kk < 128)
                ? (g_Qm + (size_t)(row0 + r) * CC + kg)
                : (g_Vm + (size_t)(row0 + r) * CC + (kg - 128));
            av = *(const uint4*)src;
        }
#pragma unroll
        for (int i = 0; i < 4; i++) {
            int f = i * 256 + t;
            int n = f >> 1, k8 = (f & 1) * 8;
            const __half* src;
            if (kk < 128) src = g_WqoT_f16 + (size_t)n * 128 + kk + k8;
            else          src = g_WoT_f16 + ((size_t)b * 512 + n) * 128 + (kk - 128) + k8;
            b4[i] = *(const uint4*)src;
        }
    };
    auto sstore = [&](int buf) {
        char* b0 = smem + buf * BUF;
        {
            int r = t >> 2, kq = (t & 3) * 4;
            float f0 = unpackf(av.x), f1 = unpackf(av.y);
            float f2 = unpackf(av.z), f3 = unpackf(av.w);
            __half2 h01 = __floats2half2_rn(f0, f1);
            __half2 h23 = __floats2half2_rn(f2, f3);
            int off = r * 48 + kq * 2;
            *(uint2*)(b0 + off) = make_uint2(*(unsigned*)&h01, *(unsigned*)&h23);
        }
#pragma unroll
        for (int i = 0; i < 4; i++) {
            int f = i * 256 + t;
            int n = f >> 1, k8 = (f & 1) * 8;
            int off = n * 48 + k8 * 2;
            *(uint4*)(b0 + 3072 + off) = b4[i];
        }
    };
    auto compute = [&](int buf) {
        const uint32_t base = sb + buf * BUF;
        uint32_t a[2][4];
        ldsm4(a[0], base + aoff);
        ldsm4(a[1], base + aoff + 768);
#pragma unroll
        for (int p = 0; p < 8; p++) {
            uint32_t bh[4];
            ldsm4(bh, base + 3072 + boff + p * 768);
#pragma unroll
            for (int q = 0; q < 2; q++)
#pragma unroll
                for (int mi = 0; mi < 2; mi++)
                    mma16816h(c[mi][2*p+q], a[mi], bh + 2*q);
        }
    };

    gload(0);
    sstore(0);
    __syncthreads();
#pragma unroll 1
    for (int cc = 0; cc < 16; cc++) {
        const int buf = cc & 1;
        if (cc < 15) gload(cc + 1);
        compute(buf);
        if (cc < 15) {
            sstore(buf ^ 1);
            __syncthreads();
        }
    }

    // ---- epilogue: bias, LN stats, normalize, store ----
#pragma unroll
    for (int mi = 0; mi < 2; mi++) {
        float sA = 0.f, qA = 0.f, sB = 0.f, qB = 0.f;
#pragma unroll
        for (int ni = 0; ni < 16; ni++) {
            int col = warpN * 128 + ni * 8 + kc;
            float b0 = bqo[col] + bo[col];
            float b1 = bqo[col + 1] + bo[col + 1];
            float x0 = c[mi][ni][0] + b0, x1 = c[mi][ni][1] + b1;
            float x2 = c[mi][ni][2] + b0, x3 = c[mi][ni][3] + b1;
            c[mi][ni][0] = x0; c[mi][ni][1] = x1;
            c[mi][ni][2] = x2; c[mi][ni][3] = x3;
            sA += x0 + x1; qA = fmaf(x0, x0, fmaf(x1, x1, qA));
            sB += x2 + x3; qB = fmaf(x2, x2, fmaf(x3, x3, qB));
        }
#pragma unroll
        for (int o = 1; o <= 2; o <<= 1) {
            sA += __shfl_xor_sync(0xffffffffu, sA, o);
            qA += __shfl_xor_sync(0xffffffffu, qA, o);
            sB += __shfl_xor_sync(0xffffffffu, sB, o);
            qB += __shfl_xor_sync(0xffffffffu, qB, o);
        }
        if (tig == 0) {
            int rl = warpM * 32 + mi * 16 + g;
            redS[warpN][rl] = sA;     redQ[warpN][rl] = qA;
            redS[warpN][rl + 8] = sB; redQ[warpN][rl + 8] = qB;
        }
    }
    __syncthreads();
#pragma unroll
    for (int mi = 0; mi < 2; mi++) {
        int rlA = warpM * 32 + mi * 16 + g;
        int rlB = rlA + 8;
        float sumA = redS[0][rlA] + redS[1][rlA] + redS[2][rlA] + redS[3][rlA];
        float sqA  = redQ[0][rlA] + redQ[1][rlA] + redQ[2][rlA] + redQ[3][rlA];
        float sumB = redS[0][rlB] + redS[1][rlB] + redS[2][rlB] + redS[3][rlB];
        float sqB  = redQ[0][rlB] + redQ[1][rlB] + redQ[2][rlB] + redQ[3][rlB];
        float muA = sumA * (1.f/512.f);
        float invA = rsqrtf(sqA * (1.f/512.f) - muA*muA + 1e-5f);
        float muB = sumB * (1.f/512.f);
        float invB = rsqrtf(sqB * (1.f/512.f) - muB*muB + 1e-5f);
#pragma unroll
        for (int ni = 0; ni < 16; ni++) {
            int col = warpN * 128 + ni * 8 + kc;
            float g0 = gamma[col], g1 = gamma[col + 1];
            float e0 = beta[col],  e1 = beta[col + 1];
            float2 vA = make_float2((c[mi][ni][0] - muA) * invA * g0 + e0,
                                    (c[mi][ni][1] - muA) * invA * g1 + e1);
            float2 vB = make_float2((c[mi][ni][2] - muB) * invB * g0 + e0,
                                    (c[mi][ni][3] - muB) * invB * g1 + e1);
            *(float2*)&Y[(size_t)(row0 + rlA) * MM + col] = vA;
            *(float2*)&Y[(size_t)(row0 + rlB) * MM + col] = vB;
        }
    }
}

// =====================================================================
extern "C" void kernel_launch(void* const* d_in, const int* in_sizes, int n_in,
                              void* d_out, int out_size)
{
    const float* Q_in  = (const float*)d_in[0];
    const float* KV_in = (const float*)d_in[1];
    const float* Wq    = (const float*)d_in[2];
    const float* bq    = (const float*)d_in[3];
    const float* Wk    = (const float*)d_in[4];
    const float* bk    = (const float*)d_in[5];
    const float* Wv    = (const float*)d_in[6];
    const float* bv    = (const float*)d_in[7];
    const float* Wo    = (const float*)d_in[8];
    const float* bo    = (const float*)d_in[9];
    const float* Wqo   = (const float*)d_in[10];
    const float* bqo   = (const float*)d_in[11];
    const float* gamma = (const float*)d_in[12];
    const float* beta  = (const float*)d_in[13];
    float* out = (float*)d_out;

    const long long y_elems = (long long)NR * MM;
    const long long a_elems = (long long)BB * HH * DK * DK;
    float* attn_out = ((long long)out_size >= y_elems + a_elems) ? (out + y_elems) : nullptr;

    const int SMQ = 2 * 30720;   // 60 KB
    const int SMF = 2 * 27648;   // 54 KB
    cudaFuncSetAttribute(k_qkv_mma,  cudaFuncAttributeMaxDynamicSharedMemorySize, SMQ);
    cudaFuncSetAttribute(k_fgemm_ln, cudaFuncAttributeMaxDynamicSharedMemorySize, SMF);

    k_prep<<<1024, 256>>>(Wq, Wk, Wv, Wqo);
    k_qkv_mma<<<dim3(NR/128, 3), 256, SMQ>>>(Q_in, KV_in, bq, bk, bv);
    k_scores<<<dim3(NCHUNK, BB*HH), 256>>>();
    k_softmax<<<BB*HH, 1024>>>(attn_out);
    k_woeff<<<dim3(MM/32, BB), 256>>>(Wo);
    k_fgemm_ln<<<NR/64, 256, SMF>>>(bqo, bo, gamma, beta, out);
}